// round 1
// baseline (speedup 1.0000x reference)
#include <cuda_runtime.h>

#define HW   16384
#define NB   2
#define CIN  128
#define CO   64
#define NK   64
#define NPIX (NB*HW)

// ---------------- scratch (static device globals; no allocation) ----------------
__device__ float g_xt[(size_t)NPIX*CO];      // [b][hw][o] pixel-major, 8 MB
__device__ float g_sums[NB*NK*CO];
__device__ int   g_cnt[NB*NK];
__device__ float g_invcov[CO*CO];
__device__ float g_adjm[NB*NK*CO];
__device__ float g_bnsum[CO];
__device__ float g_bnsq[CO];

// ---------------- Kernel 1: xt[b,hw,o] = sum_c x[b,c,hw] * Wft[c,o] ----------------
__global__ __launch_bounds__(256) void k_gemm(const float* __restrict__ x,
                                              const float* __restrict__ Wft) {
    __shared__ float ws[CIN*CO];   // 32 KB, whole Wft
    __shared__ float xs[8*256];    // 8 KB, c-chunk x pixel tile
    const int tid = threadIdx.x;
    const int P0  = blockIdx.x * 256;
    const int b   = P0 >> 14;          // / HW
    const int hw0 = P0 & (HW-1);

    for (int e = tid*4; e < CIN*CO; e += 1024)
        *(float4*)(ws+e) = *(const float4*)(Wft+e);

    const int chg = tid & 7;     // channel group (8 ch each)
    const int pxg = tid >> 3;    // pixel group (8 px each)
    float acc[8][8];
#pragma unroll
    for (int i=0;i<8;i++)
#pragma unroll
        for (int j=0;j<8;j++) acc[i][j]=0.f;

    const float* xb = x + (size_t)b*CIN*HW + hw0;

    for (int k0 = 0; k0 < CIN; k0 += 8) {
        __syncthreads();
#pragma unroll
        for (int i = 0; i < 2; i++) {
            int e4  = tid + i*256;          // 512 float4 = 8 rows x 256 px
            int row = e4 >> 6;
            int col = (e4 & 63) * 4;
            *(float4*)(xs + row*256 + col) =
                *(const float4*)(xb + (size_t)(k0+row)*HW + col);
        }
        __syncthreads();
#pragma unroll
        for (int cc = 0; cc < 8; cc++) {
            float xv[8], wv[8];
            *(float4*)(xv)   = *(float4*)(xs + cc*256 + pxg*8);
            *(float4*)(xv+4) = *(float4*)(xs + cc*256 + pxg*8 + 4);
            *(float4*)(wv)   = *(float4*)(ws + (k0+cc)*CO + chg*8);
            *(float4*)(wv+4) = *(float4*)(ws + (k0+cc)*CO + chg*8 + 4);
#pragma unroll
            for (int i=0;i<8;i++)
#pragma unroll
                for (int j=0;j<8;j++)
                    acc[i][j] = fmaf(xv[i], wv[j], acc[i][j]);
        }
    }
    float* ob = g_xt + ((size_t)b*HW + hw0)*CO;
#pragma unroll
    for (int i=0;i<8;i++) {
        int px = pxg*8 + i;
        float4 v0 = make_float4(acc[i][0],acc[i][1],acc[i][2],acc[i][3]);
        float4 v1 = make_float4(acc[i][4],acc[i][5],acc[i][6],acc[i][7]);
        *(float4*)(ob + (size_t)px*CO + chg*8)     = v0;
        *(float4*)(ob + (size_t)px*CO + chg*8 + 4) = v1;
    }
}

// ---------------- Kernel 2: per-(b,k) sums + counts via ballot scan ----------------
__global__ __launch_bounds__(256) void k_sums(const int* __restrict__ idx) {
    const int b = blockIdx.x >> 6;
    const int k = blockIdx.x & 63;
    const int w = threadIdx.x >> 5, lane = threadIdx.x & 31;
    const int* ib = idx + b*HW;
    const float2* xb = (const float2*)(g_xt + (size_t)b*HW*CO);
    float ax=0.f, ay=0.f; int cnt=0;
    const int p_end = w*2048 + 2048;
    for (int p0 = w*2048; p0 < p_end; p0 += 32) {
        int kv = ib[p0 + lane];
        unsigned m = __ballot_sync(0xffffffffu, kv == k);
        cnt += __popc(m);
        while (m) {
            int bit = __ffs(m)-1; m &= m-1;
            float2 v = xb[(size_t)(p0+bit)*32 + lane];   // channels 2*lane, 2*lane+1
            ax += v.x; ay += v.y;
        }
    }
    __shared__ float sx[8][64];
    __shared__ int   sc[8];
    sx[w][2*lane]   = ax;
    sx[w][2*lane+1] = ay;
    if (lane==0) sc[w]=cnt;
    __syncthreads();
    if (threadIdx.x < 64) {
        float s = 0.f;
#pragma unroll
        for (int i=0;i<8;i++) s += sx[i][threadIdx.x];
        g_sums[(b*NK+k)*CO + threadIdx.x] = s;
    }
    if (threadIdx.x == 0) {
        int c = 0;
#pragma unroll
        for (int i=0;i<8;i++) c += sc[i];
        g_cnt[b*NK+k] = c;
    }
}

// ---------------- Kernel 3: inv(Wm Wm^T) by Gauss-Jordan (SPD) + BN zero ----------------
__global__ __launch_bounds__(256) void k_inv(const float* __restrict__ Wm) {
    __shared__ float aug[64*128];   // 32 KB: [cov | I]
    __shared__ float colp[64];
    const int tid = threadIdx.x;
    if (tid < CO) { g_bnsum[tid]=0.f; g_bnsq[tid]=0.f; }
    for (int e = tid; e < 4096; e += 256) {
        int i = e>>6, j = e&63;
        float s = 0.f;
        for (int c=0;c<64;c+=4) {
            float4 a  = *(const float4*)(Wm + i*64 + c);
            float4 bb = *(const float4*)(Wm + j*64 + c);
            s += a.x*bb.x + a.y*bb.y + a.z*bb.z + a.w*bb.w;
        }
        aug[i*128+j]    = s;
        aug[i*128+64+j] = (i==j)?1.f:0.f;
    }
    __syncthreads();
    for (int p=0;p<64;p++) {
        if (tid < 64) colp[tid] = aug[tid*128+p];
        __syncthreads();
        if (tid < 128) {
            float pin = 1.f/colp[p];
            aug[p*128+tid] *= pin;
        }
        __syncthreads();
        for (int e = tid; e < 8192; e += 256) {
            int i = e>>7, j = e&127;
            if (i != p) aug[i*128+j] = fmaf(-colp[i], aug[p*128+j], aug[i*128+j]);
        }
        __syncthreads();
    }
    for (int e=tid;e<4096;e+=256)
        g_invcov[e] = aug[(e>>6)*128 + 64 + (e&63)];
}

// ---------------- 64x64x64 matmul helpers (256 threads, 4x4 register tiles) ----------------
__device__ __forceinline__ void mm_nn64(const float* __restrict__ A,
                                        const float* __restrict__ B,
                                        float* __restrict__ C, int tid) {
    // C[i][j] = sum_c A[i*64+c] * B[c*64+j]
    const int i0 = (tid>>4)*4, j0 = (tid&15)*4;
    float acc[4][4];
#pragma unroll
    for (int i=0;i<4;i++)
#pragma unroll
        for (int j=0;j<4;j++) acc[i][j]=0.f;
    for (int c0=0;c0<64;c0+=4) {
        float4 av[4], bv[4];
#pragma unroll
        for (int ii=0;ii<4;ii++) av[ii] = *(const float4*)(A + (i0+ii)*64 + c0);
#pragma unroll
        for (int cc=0;cc<4;cc++) bv[cc] = *(const float4*)(B + (c0+cc)*64 + j0);
#pragma unroll
        for (int ii=0;ii<4;ii++) {
            const float* ap = (const float*)&av[ii];
#pragma unroll
            for (int cc=0;cc<4;cc++) {
                float a = ap[cc];
                acc[ii][0] = fmaf(a, bv[cc].x, acc[ii][0]);
                acc[ii][1] = fmaf(a, bv[cc].y, acc[ii][1]);
                acc[ii][2] = fmaf(a, bv[cc].z, acc[ii][2]);
                acc[ii][3] = fmaf(a, bv[cc].w, acc[ii][3]);
            }
        }
    }
#pragma unroll
    for (int ii=0;ii<4;ii++)
        *(float4*)(C + (i0+ii)*64 + j0) =
            make_float4(acc[ii][0],acc[ii][1],acc[ii][2],acc[ii][3]);
}

__device__ __forceinline__ void mm_nt64(const float* __restrict__ A,
                                        const float* __restrict__ B,
                                        float* __restrict__ C, int tid) {
    // C[i][j] = sum_c A[i*64+c] * B[j*64+c]
    const int i0 = (tid>>4)*4, j0 = (tid&15)*4;
    float acc[4][4];
#pragma unroll
    for (int i=0;i<4;i++)
#pragma unroll
        for (int j=0;j<4;j++) acc[i][j]=0.f;
    for (int c0=0;c0<64;c0+=4) {
        float4 av[4], bv[4];
#pragma unroll
        for (int ii=0;ii<4;ii++) av[ii] = *(const float4*)(A + (i0+ii)*64 + c0);
#pragma unroll
        for (int jj=0;jj<4;jj++) bv[jj] = *(const float4*)(B + (j0+jj)*64 + c0);
#pragma unroll
        for (int ii=0;ii<4;ii++)
#pragma unroll
            for (int jj=0;jj<4;jj++) {
                acc[ii][jj] = fmaf(av[ii].x, bv[jj].x, acc[ii][jj]);
                acc[ii][jj] = fmaf(av[ii].y, bv[jj].y, acc[ii][jj]);
                acc[ii][jj] = fmaf(av[ii].z, bv[jj].z, acc[ii][jj]);
                acc[ii][jj] = fmaf(av[ii].w, bv[jj].w, acc[ii][jj]);
            }
    }
#pragma unroll
    for (int ii=0;ii<4;ii++)
        *(float4*)(C + (i0+ii)*64 + j0) =
            make_float4(acc[ii][0],acc[ii][1],acc[ii][2],acc[ii][3]);
}

// ---------------- Kernel 4: means -> G -> adj -> adj_means (per batch) ----------------
__global__ __launch_bounds__(256) void k_adj() {
    __shared__ float M[4096], AG[4096], T[4096];   // 48 KB exactly
    const int b = blockIdx.x;
    const int tid = threadIdx.x;
    for (int e=tid;e<4096;e+=256) {
        int k = e>>6;
        float c = (float)g_cnt[b*NK+k];
        float denom = (c>0.f) ? c : 1.f;
        M[e]  = g_sums[b*4096+e] / denom;
        AG[e] = g_invcov[e];
    }
    __syncthreads();
    mm_nn64(M, AG, T, tid);        // T = M * A
    __syncthreads();
    mm_nt64(T, M, AG, tid);        // AG = G = T * M^T   (A dead)
    __syncthreads();
    if (tid < 64) T[tid] = AG[tid*65];   // diag(G) into (dead) T
    __syncthreads();
    for (int e=tid;e<4096;e+=256) {
        int i=e>>6, j=e&63;
        float q = T[i] + T[j] - 2.f*AG[e];
        AG[e] = expf(-sqrtf(fmaxf(q, 1e-12f)));
    }
    __syncthreads();
    mm_nn64(AG, M, g_adjm + b*4096, tid);   // adj_means = adj * M
}

// ---------------- Kernel 5: features = relu(xt + adjm[idx]) -> d_out, BN stats ----------------
__global__ __launch_bounds__(256) void k_feat(const int* __restrict__ idx,
                                              float* __restrict__ out) {
    __shared__ float am[4096];      // [k][o ^ (k&31)] swizzled    16 KB
    __shared__ float xts[64*128];   // [o][px ^ ((o>>2)&31)]       32 KB
    const int tid = threadIdx.x;
    const int P0  = blockIdx.x*128;
    const int b   = P0 >> 14;
    const int hw0 = P0 & (HW-1);

    for (int e=tid;e<4096;e+=256) {
        int k=e>>6, o=e&63;
        am[k*64 + (o ^ (k&31))] = g_adjm[b*4096+e];
    }
    const float* xb = g_xt + ((size_t)b*HW + hw0)*CO;
    for (int e4=tid;e4<2048;e4+=256) {
        float4 v = ((const float4*)xb)[e4];
        int flat = e4*4;
        int px = flat>>6;
        int o  = flat&63;
        int sw = (o>>2)&31;           // same for o..o+3
        xts[(o+0)*128 + (px^sw)] = v.x;
        xts[(o+1)*128 + (px^sw)] = v.y;
        xts[(o+2)*128 + (px^sw)] = v.z;
        xts[(o+3)*128 + (px^sw)] = v.w;
    }
    __syncthreads();
    const int w = tid>>5, lane = tid&31;
    float* ob = out + (size_t)b*CO*HW + hw0;
    float bs[8], bq[8];
#pragma unroll
    for (int oo=0;oo<8;oo++){ bs[oo]=0.f; bq[oo]=0.f; }
#pragma unroll
    for (int pp=0;pp<4;pp++) {
        int px = lane + pp*32;
        int k  = idx[b*HW + hw0 + px];
        int ksw = k&31;
#pragma unroll
        for (int oo=0;oo<8;oo++) {
            int o = w*8+oo;
            float v = xts[o*128 + (px ^ ((o>>2)&31))] + am[k*64 + (o ^ ksw)];
            v = fmaxf(v, 0.f);
            ob[(size_t)o*HW + px] = v;
            bs[oo] += v; bq[oo] += v*v;
        }
    }
#pragma unroll
    for (int oo=0;oo<8;oo++) {
        float s=bs[oo], q=bq[oo];
#pragma unroll
        for (int off=16;off;off>>=1) {
            s += __shfl_down_sync(0xffffffffu, s, off);
            q += __shfl_down_sync(0xffffffffu, q, off);
        }
        if (lane==0) {
            atomicAdd(&g_bnsum[w*8+oo], s);
            atomicAdd(&g_bnsq [w*8+oo], q);
        }
    }
}

// ---------------- Kernel 6: in-place batchnorm on d_out ----------------
__global__ __launch_bounds__(256) void k_bn(float* __restrict__ out,
                                            const float* __restrict__ gamma,
                                            const float* __restrict__ beta) {
    __shared__ float ssc[64], sbi[64];
    const int tid = threadIdx.x;
    if (tid < 64) {
        const float invN = 1.f/(float)NPIX;
        float mean = g_bnsum[tid]*invN;
        float var  = g_bnsq[tid]*invN - mean*mean;
        float sc   = gamma[tid]*rsqrtf(var + 1e-5f);
        ssc[tid]=sc;
        sbi[tid]=beta[tid] - mean*sc;
    }
    __syncthreads();
    float4* o4 = (float4*)out;
    const int n4 = NPIX*CO/4;
    for (int i4 = blockIdx.x*256 + tid; i4 < n4; i4 += gridDim.x*256) {
        int c = (i4 >> 12) & 63;     // (flat/16384)%64
        float4 v = o4[i4];
        float sc = ssc[c], bi = sbi[c];
        v.x=fmaf(v.x,sc,bi); v.y=fmaf(v.y,sc,bi);
        v.z=fmaf(v.z,sc,bi); v.w=fmaf(v.w,sc,bi);
        o4[i4] = v;
    }
}

// ---------------- launch ----------------
extern "C" void kernel_launch(void* const* d_in, const int* in_sizes, int n_in,
                              void* d_out, int out_size) {
    const float* x     = (const float*)d_in[0];
    const int*   index = (const int*)  d_in[1];
    const float* Wft   = (const float*)d_in[2];
    const float* Wm    = (const float*)d_in[3];
    const float* gamma = (const float*)d_in[4];
    const float* beta  = (const float*)d_in[5];
    float* out = (float*)d_out;

    k_gemm<<<NPIX/256, 256>>>(x, Wft);
    k_sums<<<NB*NK,    256>>>(index);
    k_inv <<<1,        256>>>(Wm);
    k_adj <<<NB,       256>>>();
    k_feat<<<NPIX/128, 256>>>(index, out);
    k_bn  <<<512,      256>>>(out, gamma, beta);
}

// round 2
// speedup vs baseline: 1.7392x; 1.7392x over previous
#include <cuda_runtime.h>

#define HW   16384
#define NB   2
#define CIN  128
#define CO   64
#define NK   64
#define NPIX (NB*HW)

// accumulator pack (single memset target)
#define ACC_SUMS  0        // 8192 floats: [b][k][o]
#define ACC_CNT   8192     // 128 floats:  [b][k]
#define ACC_BNSUM 8320     // 64
#define ACC_BNSQ  8384     // 64
#define ACCN      8448

// ---------------- scratch (static device globals; no allocation) ----------------
__device__ float g_xt[(size_t)NPIX*CO];      // [b][hw][o] pixel-major, 8 MB (L2-resident)
__device__ float g_acc[ACCN];
__device__ float g_invcov[CO*CO];
__device__ float g_means[NB*NK*CO];
__device__ float g_T[NB*NK*CO];
__device__ float g_diag[NB*NK];
__device__ float g_adjm[NB*NK*CO];

// ---------------- Blackwell helpers ----------------
__device__ __forceinline__ unsigned long long pk2(float v) {
    unsigned long long r; unsigned u = __float_as_uint(v);
    asm("mov.b64 %0, {%1, %2};" : "=l"(r) : "r"(u), "r"(u));
    return r;
}
__device__ __forceinline__ void ffma2(unsigned long long& d,
                                      unsigned long long a, unsigned long long b) {
    asm("fma.rn.f32x2 %0, %1, %2, %3;" : "=l"(d) : "l"(a), "l"(b), "l"(d));
}
__device__ __forceinline__ void red4(float* p, float a, float b, float c, float d) {
    asm volatile("red.add.v4.f32 [%0], {%1, %2, %3, %4};"
                 :: "l"(p), "f"(a), "f"(b), "f"(c), "f"(d) : "memory");
}

// ---------------- Kernel 1: GEMM (blocks 0..127) + cov inverse (block 128) ----------------
// GEMM: xt[b,hw,o] = sum_c x[b,c,hw]*Wft[c,o], f32x2 packed FMA.
// Fused: per-(b,k) sums via vector global reds, counts via smem hist.
// Block 128: inv(Wm Wm^T) by Gauss-Jordan (SPD, no pivoting), 2 barriers/pivot.
__global__ __launch_bounds__(256) void k_main(const float* __restrict__ x,
                                              const float* __restrict__ Wft,
                                              const int*   __restrict__ idx,
                                              const float* __restrict__ Wm) {
    __shared__ float sm[8448];   // 33 KB union
    const int tid = threadIdx.x;

    if (blockIdx.x == 128) {
        // ---- inversion path ----
        float* aug  = sm;          // 64 x 128
        float* colp = sm + 8192;   // 64
        float* prow = sm + 8256;   // 128
        for (int e = tid; e < 4096; e += 256) {
            int i = e >> 6, j = e & 63;
            float s = 0.f;
            for (int c = 0; c < 64; c += 4) {
                float4 a  = *(const float4*)(Wm + i*64 + c);
                float4 bb = *(const float4*)(Wm + j*64 + c);
                s += a.x*bb.x + a.y*bb.y + a.z*bb.z + a.w*bb.w;
            }
            aug[i*128 + j]      = s;
            aug[i*128 + 64 + j] = (i == j) ? 1.f : 0.f;
        }
        __syncthreads();
        for (int p = 0; p < 64; p++) {
            if (tid < 64) {
                colp[tid] = aug[tid*128 + p];
            } else if (tid < 192) {
                int j = tid - 64;
                prow[j] = aug[p*128 + j] * (1.f / aug[p*128 + p]);
            }
            __syncthreads();
            for (int e = tid; e < 8192; e += 256) {
                int i = e >> 7, j = e & 127;
                float pr = prow[j];
                aug[e] = (i == p) ? pr : fmaf(-colp[i], pr, aug[e]);
            }
            __syncthreads();
        }
        for (int e = tid; e < 4096; e += 256)
            g_invcov[e] = aug[(e>>6)*128 + 64 + (e&63)];
        return;
    }

    // ---- GEMM path ----
    float* xs   = sm;                 // 2048: 8 ch x 256 px
    float* wsc  = sm + 2048;          // 512:  8 ch x 64 o
    float* scnt = sm + 2560;          // 64
    int*   sidx = (int*)(sm + 2624);  // 256

    const int P0  = blockIdx.x * 256;
    const int b   = P0 >> 14;
    const int hw0 = P0 & (HW-1);

    if (tid < 64) {
        scnt[tid] = 0.f;
        ((int4*)sidx)[tid] = ((const int4*)(idx + P0))[tid];
    }

    const int chg = tid & 7;     // channel group (8 ch)
    const int pxg = tid >> 3;    // pixel group (8 px)
    unsigned long long acc2[8][4];
#pragma unroll
    for (int i = 0; i < 8; i++)
#pragma unroll
        for (int j = 0; j < 4; j++) acc2[i][j] = 0ull;

    const float* xb = x + (size_t)b*CIN*HW + hw0;

    for (int k0 = 0; k0 < CIN; k0 += 8) {
        __syncthreads();
#pragma unroll
        for (int i = 0; i < 2; i++) {
            int e4  = tid + i*256;
            int row = e4 >> 6;
            int col = (e4 & 63) * 4;
            *(float4*)(xs + row*256 + col) =
                *(const float4*)(xb + (size_t)(k0+row)*HW + col);
        }
        if (tid < 128)
            ((float4*)wsc)[tid] = ((const float4*)(Wft + k0*CO))[tid];
        __syncthreads();
#pragma unroll
        for (int cc = 0; cc < 8; cc++) {
            float xv[8];
            *(float4*)(xv)   = *(float4*)(xs + cc*256 + pxg*8);
            *(float4*)(xv+4) = *(float4*)(xs + cc*256 + pxg*8 + 4);
            ulonglong2 wA = *(ulonglong2*)(wsc + cc*64 + chg*8);      // ch pairs (0,1),(2,3)
            ulonglong2 wB = *(ulonglong2*)(wsc + cc*64 + chg*8 + 4);  // ch pairs (4,5),(6,7)
#pragma unroll
            for (int i = 0; i < 8; i++) {
                unsigned long long ax = pk2(xv[i]);
                ffma2(acc2[i][0], ax, wA.x);
                ffma2(acc2[i][1], ax, wA.y);
                ffma2(acc2[i][2], ax, wB.x);
                ffma2(acc2[i][3], ax, wB.y);
            }
        }
    }

    float* ob = g_xt + ((size_t)b*HW + hw0)*CO;
#pragma unroll
    for (int i = 0; i < 8; i++) {
        int px = pxg*8 + i;
        unsigned long long a0 = acc2[i][0], a1 = acc2[i][1],
                           a2 = acc2[i][2], a3 = acc2[i][3];
        float v0 = __uint_as_float((unsigned)a0), v1 = __uint_as_float((unsigned)(a0>>32));
        float v2 = __uint_as_float((unsigned)a1), v3 = __uint_as_float((unsigned)(a1>>32));
        float v4 = __uint_as_float((unsigned)a2), v5 = __uint_as_float((unsigned)(a2>>32));
        float v6 = __uint_as_float((unsigned)a3), v7 = __uint_as_float((unsigned)(a3>>32));
        *(float4*)(ob + (size_t)px*CO + chg*8)     = make_float4(v0,v1,v2,v3);
        *(float4*)(ob + (size_t)px*CO + chg*8 + 4) = make_float4(v4,v5,v6,v7);
        int k = sidx[px];
        float* sp = g_acc + ACC_SUMS + ((b*NK + k)*CO + chg*8);
        red4(sp,     v0,v1,v2,v3);
        red4(sp + 4, v4,v5,v6,v7);
        if (chg == 0) atomicAdd(&scnt[k], 1.f);
    }
    __syncthreads();
    if (tid < 64) atomicAdd(&g_acc[ACC_CNT + b*64 + tid], scnt[tid]);
}

// ---------------- Kernel 2: means, T = means*invcov, diag (16 blocks x 8 rows) ----------------
__global__ __launch_bounds__(256) void k_adjA() {
    __shared__ float As[4096], mR[512], tR[512];
    const int tid = threadIdx.x;
    const int b = blockIdx.x >> 3, r0 = (blockIdx.x & 7) * 8;

    for (int e = tid; e < 1024; e += 256)
        ((float4*)As)[e] = ((const float4*)g_invcov)[e];
    for (int e = tid; e < 512; e += 256) {
        int rl = e >> 6;
        float c = g_acc[ACC_CNT + b*64 + r0 + rl];
        float v = g_acc[ACC_SUMS + b*4096 + r0*64 + e] / ((c > 0.f) ? c : 1.f);
        mR[e] = v;
        g_means[b*4096 + r0*64 + e] = v;
    }
    __syncthreads();
    {
        int il0 = tid >> 6, j = tid & 63, il1 = il0 + 4;
        float a0 = 0.f, a1 = 0.f;
        for (int c = 0; c < 64; c++) {
            float Ac = As[c*64 + j];
            a0 = fmaf(mR[il0*64 + c], Ac, a0);
            a1 = fmaf(mR[il1*64 + c], Ac, a1);
        }
        tR[il0*64 + j] = a0;  tR[il1*64 + j] = a1;
        g_T[b*4096 + (r0+il0)*64 + j] = a0;
        g_T[b*4096 + (r0+il1)*64 + j] = a1;
    }
    __syncthreads();
    if (tid < 8) {
        float d = 0.f;
        for (int c = 0; c < 64; c++)
            d = fmaf(tR[tid*64 + c], mR[tid*64 + c], d);
        g_diag[b*64 + r0 + tid] = d;
    }
}

// ---------------- Kernel 3: G -> adj = exp(-sqrt(q)) -> adjm = adj*means ----------------
__global__ __launch_bounds__(256) void k_adjB() {
    __shared__ float Ms[4096];      // mean[j][c] at Ms[c*64 + (j^(c&31))]
    __shared__ float tRb[512], sadj[512], dg[64];
    const int tid = threadIdx.x;
    const int b = blockIdx.x >> 3, r0 = (blockIdx.x & 7) * 8;

    for (int e = tid; e < 4096; e += 256) {
        int j = e >> 6, c = e & 63;
        Ms[c*64 + (j ^ (c & 31))] = g_means[b*4096 + e];
    }
    for (int e = tid; e < 512; e += 256)
        tRb[e] = g_T[b*4096 + r0*64 + e];
    if (tid < 64) dg[tid] = g_diag[b*64 + tid];
    __syncthreads();
    {
        int il0 = tid >> 6, j = tid & 63, il1 = il0 + 4;
        float a0 = 0.f, a1 = 0.f;
        for (int c = 0; c < 64; c++) {
            float mv = Ms[c*64 + (j ^ (c & 31))];
            a0 = fmaf(tRb[il0*64 + c], mv, a0);
            a1 = fmaf(tRb[il1*64 + c], mv, a1);
        }
        float q0 = dg[r0+il0] + dg[j] - 2.f*a0;
        float q1 = dg[r0+il1] + dg[j] - 2.f*a1;
        sadj[il0*64 + j] = expf(-sqrtf(fmaxf(q0, 1e-12f)));
        sadj[il1*64 + j] = expf(-sqrtf(fmaxf(q1, 1e-12f)));
    }
    __syncthreads();
    {
        int il0 = tid >> 6, o = tid & 63, il1 = il0 + 4;
        float a0 = 0.f, a1 = 0.f;
        for (int jj = 0; jj < 64; jj++) {
            float mv = Ms[o*64 + (jj ^ (o & 31))];
            a0 = fmaf(sadj[il0*64 + jj], mv, a0);
            a1 = fmaf(sadj[il1*64 + jj], mv, a1);
        }
        g_adjm[b*4096 + (r0+il0)*64 + o] = a0;
        g_adjm[b*4096 + (r0+il1)*64 + o] = a1;
    }
}

// ---------------- Kernel 4: BN stats over relu(xt + adjm[idx]) (no feature write) ----------------
__global__ __launch_bounds__(256) void k_stats(const int* __restrict__ idx) {
    __shared__ float am[4096];
    __shared__ float red[2048];
    __shared__ int   sidx[256];
    const int tid = threadIdx.x;
    const int P0  = blockIdx.x * 256;
    const int b   = P0 >> 14;

    for (int e = tid; e < 1024; e += 256)
        ((float4*)am)[e] = ((const float4*)(g_adjm + b*4096))[e];
    if (tid < 64) ((int4*)sidx)[tid] = ((const int4*)(idx + P0))[tid];
    __syncthreads();

    const int pr = tid >> 4, c4 = tid & 15;
    const float4* xb = (const float4*)(g_xt + (size_t)P0*CO);
    float4 s4 = make_float4(0,0,0,0), q4 = make_float4(0,0,0,0);
#pragma unroll 4
    for (int it = 0; it < 16; it++) {
        int px = it*16 + pr;
        int k  = sidx[px];
        float4 xv = xb[px*16 + c4];
        float4 av = ((float4*)am)[k*16 + c4];
        float v0 = fmaxf(xv.x+av.x, 0.f), v1 = fmaxf(xv.y+av.y, 0.f);
        float v2 = fmaxf(xv.z+av.z, 0.f), v3 = fmaxf(xv.w+av.w, 0.f);
        s4.x += v0; s4.y += v1; s4.z += v2; s4.w += v3;
        q4.x += v0*v0; q4.y += v1*v1; q4.z += v2*v2; q4.w += v3*v3;
    }
    ((float4*)red)[pr*16 + c4] = s4;
    ((float4*)(red + 1024))[pr*16 + c4] = q4;
    __syncthreads();
    if (tid < 64) {
        float s = 0.f, q = 0.f;
#pragma unroll
        for (int p = 0; p < 16; p++) { s += red[p*64 + tid]; q += red[1024 + p*64 + tid]; }
        atomicAdd(&g_acc[ACC_BNSUM + tid], s);
        atomicAdd(&g_acc[ACC_BNSQ  + tid], q);
    }
}

// ---------------- Kernel 5: recompute features, normalize, write out (channel-major) ----------------
__global__ __launch_bounds__(256) void k_final(const int* __restrict__ idx,
                                               float* __restrict__ out,
                                               const float* __restrict__ gamma,
                                               const float* __restrict__ beta) {
    __shared__ float am[4096];      // [k][o ^ (k&31)]
    __shared__ float xts[64*128];   // [o][px ^ ((o>>2)&31)]
    const int tid = threadIdx.x;
    const int P0  = blockIdx.x * 128;
    const int b   = P0 >> 14;
    const int hw0 = P0 & (HW-1);

    for (int e = tid; e < 4096; e += 256) {
        int k = e >> 6, o = e & 63;
        am[k*64 + (o ^ (k & 31))] = g_adjm[b*4096 + e];
    }
    const float* xb = g_xt + ((size_t)b*HW + hw0)*CO;
    for (int e4 = tid; e4 < 2048; e4 += 256) {
        float4 v = ((const float4*)xb)[e4];
        int flat = e4*4;
        int px = flat >> 6;
        int o  = flat & 63;
        int sw = (o >> 2) & 31;
        xts[(o+0)*128 + (px^sw)] = v.x;
        xts[(o+1)*128 + (px^sw)] = v.y;
        xts[(o+2)*128 + (px^sw)] = v.z;
        xts[(o+3)*128 + (px^sw)] = v.w;
    }
    const int w = tid >> 5, lane = tid & 31;
    float sc[8], bi[8];
    const float invN = 1.f/(float)NPIX;
#pragma unroll
    for (int oo = 0; oo < 8; oo++) {
        int o = w*8 + oo;
        float mean = g_acc[ACC_BNSUM + o]*invN;
        float var  = g_acc[ACC_BNSQ  + o]*invN - mean*mean;
        float s = gamma[o]*rsqrtf(var + 1e-5f);
        sc[oo] = s; bi[oo] = beta[o] - mean*s;
    }
    __syncthreads();

    float* ob = out + (size_t)b*CO*HW + hw0;
#pragma unroll
    for (int pp = 0; pp < 4; pp++) {
        int px = lane + pp*32;
        int k  = idx[P0 + px];
        int ksw = k & 31;
#pragma unroll
        for (int oo = 0; oo < 8; oo++) {
            int o = w*8 + oo;
            float v = xts[o*128 + (px ^ ((o>>2)&31))] + am[k*64 + (o ^ ksw)];
            v = fmaxf(v, 0.f);
            ob[(size_t)o*HW + px] = fmaf(v, sc[oo], bi[oo]);
        }
    }
}

// ---------------- launch ----------------
extern "C" void kernel_launch(void* const* d_in, const int* in_sizes, int n_in,
                              void* d_out, int out_size) {
    const float* x     = (const float*)d_in[0];
    const int*   index = (const int*)  d_in[1];
    const float* Wft   = (const float*)d_in[2];
    const float* Wm    = (const float*)d_in[3];
    const float* gamma = (const float*)d_in[4];
    const float* beta  = (const float*)d_in[5];
    float* out = (float*)d_out;

    void* accp = nullptr;
    cudaGetSymbolAddress(&accp, g_acc);
    cudaMemsetAsync(accp, 0, ACCN*sizeof(float));

    k_main <<<129, 256>>>(x, Wft, index, Wm);
    k_adjA <<<16,  256>>>();
    k_adjB <<<16,  256>>>();
    k_stats<<<128, 256>>>(index);
    k_final<<<256, 256>>>(index, out, gamma, beta);
}